// round 15
// baseline (speedup 1.0000x reference)
#include <cuda_runtime.h>
#include <cstdint>

#define NN 500
#define GG 128
#define HH 200
#define WW 304
#define HWPX (HH * WW)            // 60800
#define WORDS 1900                // HWPX/32 exact
#define WSTRIDE 1920              // padded bit-row stride (u32), 16B multiple
#define MAXPAIRS (NN * (NN - 1) / 2)
#define MASK_THR 0.005f
#define SIGMA 2.0f

#define NCHUNK 20                 // chunks per grid row
#define CHUNKW 96                 // words per chunk (last chunk: 76). multiple of 4.

#define POPC_BLOCKS 1216
#define CELLS_PER_CTA ((NN * NN + POPC_BLOCKS - 1) / POPC_BLOCKS)   // 206
#define LMAX 224

// ---- device scratch (zero-init at load; decayfinal resets per replay) ----
__device__ __align__(16) unsigned int g_bits[NN * WSTRIDE];
__device__ float g_areaf[NN];             // exact small-int float sums
__device__ float g_ssum[NN];              // soft*hard sums (atomic accumulated)
__device__ float g_comp[NN];              // comp_iou (0 at entry)
__device__ int   g_npairs;                // 0 at entry
__device__ unsigned int g_pair_ij[MAXPAIRS];
__device__ float g_pair_d[MAXPAIRS];

// process one quad: ballots + predicated sums + lane-0 STG.128
#define PROC(A, B, K) do {                                               \
    const float s0 = (A).x * (B).x, s1 = (A).y * (B).y;                  \
    const float s2 = (A).z * (B).z, s3 = (A).w * (B).w;                  \
    const bool p0 = s0 > MASK_THR, p1 = s1 > MASK_THR;                   \
    const bool p2 = s2 > MASK_THR, p3 = s3 > MASK_THR;                   \
    const unsigned c0 = __ballot_sync(0xffffffffu, p0);                  \
    const unsigned c1 = __ballot_sync(0xffffffffu, p1);                  \
    const unsigned c2 = __ballot_sync(0xffffffffu, p2);                  \
    const unsigned c3 = __ballot_sync(0xffffffffu, p3);                  \
    if (p0) { ssum += s0; areaf += 1.0f; }                               \
    if (p1) { ssum += s1; areaf += 1.0f; }                               \
    if (p2) { ssum += s2; areaf += 1.0f; }                               \
    if (p3) { ssum += s3; areaf += 1.0f; }                               \
    if (lane == 0) pwB[K] = make_uint4(c0, c1, c2, c3);                  \
} while (0)

// ============================================================
// Kernel 1: decode, x-row-stationary with R7 warp parallelism and
// NO block syncs in the mask loop. CTA = (x-row, chunk); x chunk in
// smem; all 8 warps stripe each mask's quads; each warp finishes a
// mask with warp-reduce + lane-0 float atomicAdd (order variation
// ~1e-7, far inside 1e-3 gate). Bits in ballot order (fixed pixel
// permutation: invariant for AND/popc/area/sums).
// ============================================================
__global__ __launch_bounds__(256) void decode_kernel(
    const float* __restrict__ segx,
    const float* __restrict__ segy,
    const int* __restrict__ x_inds,
    const int* __restrict__ y_inds)
{
    __shared__ float sx[CHUNKW * 32];     // 12 KB
    __shared__ int   s_list[NN];
    __shared__ int   s_cnt;

    const int row  = blockIdx.x / NCHUNK;
    const int c    = blockIdx.x - row * NCHUNK;
    const int tid  = threadIdx.x;
    const int warp = tid >> 5;
    const int lane = tid & 31;

    if (tid == 0) s_cnt = 0;
    __syncthreads();
    for (int k = tid; k < NN; k += 256)
        if (x_inds[k] == row) {
            int pos = atomicAdd(&s_cnt, 1);
            s_list[pos] = k;
        }
    __syncthreads();
    const int cnt = s_cnt;
    if (cnt == 0) return;

    const int w0 = c * CHUNKW;
    const int nquads = ((c == NCHUNK - 1) ? (WORDS - w0) : CHUNKW) >> 2;   // 24 or 19
    const int nf4 = nquads * 32;

    // load x chunk into smem (coalesced float4)
    const float4* __restrict__ rx4 =
        reinterpret_cast<const float4*>(segx + (size_t)row * HWPX) + w0 * 8;
    for (int i = tid; i < nf4; i += 256)
        reinterpret_cast<float4*>(sx)[i] = rx4[i];
    __syncthreads();

    const float4* __restrict__ sx4 = reinterpret_cast<const float4*>(sx);

    // mask loop: warps run it independently (no more block syncs)
    for (int g = 0; g < cnt; g++) {
        const int m  = s_list[g];
        const float4* __restrict__ by =
            reinterpret_cast<const float4*>(segy + (size_t)y_inds[m] * HWPX) + w0 * 8 + lane;
        uint4* pwB = reinterpret_cast<uint4*>(g_bits + m * WSTRIDE + w0);

        float ssum  = 0.0f;
        float areaf = 0.0f;

        int k = warp;
        for (; k + 8 < nquads; k += 16) {
            const float4 a0 = sx4[32 * k + lane];
            const float4 b0 = by[32 * k];
            const float4 a1 = sx4[32 * (k + 8) + lane];
            const float4 b1 = by[32 * (k + 8)];
            PROC(a0, b0, k);
            PROC(a1, b1, k + 8);
        }
        if (k < nquads) {
            const float4 a0 = sx4[32 * k + lane];
            const float4 b0 = by[32 * k];
            PROC(a0, b0, k);
        }

        // per-warp reduce + atomic accumulate (no block sync)
#pragma unroll
        for (int off = 16; off > 0; off >>= 1) {
            ssum  += __shfl_down_sync(0xffffffffu, ssum,  off);
            areaf += __shfl_down_sync(0xffffffffu, areaf, off);
        }
        if (lane == 0) {
            atomicAdd(&g_ssum[m],  ssum);
            atomicAdd(&g_areaf[m], areaf);
        }
        // last chunk zeroes this mask's pad words [1900,1920)
        if (c == NCHUNK - 1 && warp == 0 && lane < WSTRIDE - WORDS)
            g_bits[m * WSTRIDE + WORDS + lane] = 0u;
    }
}

// ============================================================
// Kernel 2: popc with CTA-local pair building (R14 form).
// ============================================================
__global__ __launch_bounds__(256) void popc_kernel(const int* __restrict__ labels)
{
    __shared__ int s_lab[NN];
    __shared__ unsigned s_pairs[LMAX];
    __shared__ int s_cnt;
    const int tid  = threadIdx.x;
    const int lane = tid & 31;
    const int warp = tid >> 5;

    if (tid == 0) s_cnt = 0;
    for (int q = tid; q < NN; q += 256) s_lab[q] = labels[q];
    __syncthreads();

    const int lo = blockIdx.x * CELLS_PER_CTA;
    const int hi = min(lo + CELLS_PER_CTA, NN * NN);

    for (int p = lo + tid; p < hi; p += 256) {
        const int i = p / NN;
        const int j = p - i * NN;
        if (j > i && s_lab[i] == s_lab[j]) {
            int pos = atomicAdd(&s_cnt, 1);
            s_pairs[pos] = ((unsigned)i << 16) | (unsigned)j;
        }
    }
    __syncthreads();
    const int cnt = s_cnt;

    for (int q = warp; q < cnt; q += 8) {
        const unsigned ij = s_pairs[q];
        const int i = (int)(ij >> 16);
        const int j = (int)(ij & 0xffffu);

        const uint4* __restrict__ bi = reinterpret_cast<const uint4*>(g_bits + i * WSTRIDE);
        const uint4* __restrict__ bj = reinterpret_cast<const uint4*>(g_bits + j * WSTRIDE);

        int inter = 0;
#pragma unroll 5
        for (int w = lane; w < WSTRIDE / 4; w += 32) {   // 15 iterations
            uint4 a = bi[w];
            uint4 b = bj[w];
            inter += __popc(a.x & b.x) + __popc(a.y & b.y)
                   + __popc(a.z & b.z) + __popc(a.w & b.w);
        }
#pragma unroll
        for (int off = 16; off > 0; off >>= 1)
            inter += __shfl_down_sync(0xffffffffu, inter, off);

        if (lane == 0) {
            float uni = g_areaf[i] + g_areaf[j] - (float)inter;
            float iou = (float)inter / fmaxf(uni, 1e-6f);
            atomicMax(reinterpret_cast<int*>(&g_comp[j]), __float_as_int(iou)); // iou>=0
            int pos = atomicAdd(&g_npairs, 1);
            g_pair_ij[pos] = ij;
            g_pair_d[pos] = iou;
        }
    }
}

// ============================================================
// Kernel 3 (single block, tiny data): scores + decay + output + reset.
// ============================================================
__global__ __launch_bounds__(1024) void decayfinal_kernel(
    const float* __restrict__ cate_scores,
    float* __restrict__ out)
{
    __shared__ float s_coef[NN];
    __shared__ float s_score[NN];
    const int tid = threadIdx.x;

    for (int n = tid; n < NN; n += 1024) {
        s_score[n] = cate_scores[n] * (g_ssum[n] / fmaxf(g_areaf[n], 1.0f));
        s_coef[n] = 1.0f;
    }
    __syncthreads();

    const int np = g_npairs;
    for (int p = tid; p < np; p += 1024) {
        const unsigned ij = g_pair_ij[p];
        const int i = (int)(ij >> 16);
        const int j = (int)(ij & 0xffffu);
        const float d = g_pair_d[p];
        const float c = g_comp[i];
        const float term = __expf(SIGMA * (c * c - d * d));   // > 0
        atomicMin(reinterpret_cast<int*>(&s_coef[j]), __float_as_int(term));
    }
    __syncthreads();

    for (int n = tid; n < NN; n += 1024) {
        out[n] = s_score[n] * fminf(s_coef[n], 1.0f);
        g_areaf[n] = 0.0f;
        g_ssum[n]  = 0.0f;
        g_comp[n]  = 0.0f;
    }
    if (tid == 0) g_npairs = 0;
}

extern "C" void kernel_launch(void* const* d_in, const int* in_sizes, int n_in,
                              void* d_out, int out_size)
{
    const float* cate_scores = (const float*)d_in[0];
    const float* segx        = (const float*)d_in[1];
    const float* segy        = (const float*)d_in[2];
    const int*   labels      = (const int*)d_in[3];
    const int*   x_inds      = (const int*)d_in[4];
    const int*   y_inds      = (const int*)d_in[5];
    float* out = (float*)d_out;

    decode_kernel<<<GG * NCHUNK, 256>>>(segx, segy, x_inds, y_inds);
    popc_kernel<<<POPC_BLOCKS, 256>>>(labels);
    decayfinal_kernel<<<1, 1024>>>(cate_scores, out);
}

// round 16
// speedup vs baseline: 1.1757x; 1.1757x over previous
#include <cuda_runtime.h>
#include <cstdint>

#define NN 500
#define GG 128
#define HH 200
#define WW 304
#define HWPX (HH * WW)            // 60800
#define WORDS 1900                // HWPX/32 exact
#define WSTRIDE 1920              // padded bit-row stride (u32), 16B multiple
#define MAXPAIRS (NN * (NN - 1) / 2)
#define MASK_THR 0.005f
#define SIGMA 2.0f

#define NCHUNK 12                 // chunks per mask: grid 6000
#define CHUNKW 160                // words per chunk (last chunk: 140). multiple of 4.

#define POPC_BLOCKS 1216
#define CELLS_PER_CTA ((NN * NN + POPC_BLOCKS - 1) / POPC_BLOCKS)   // 206
#define LMAX 224

// ---- device scratch (zero-init at load; fused final phase resets per replay) ----
__device__ __align__(16) unsigned int g_bits[NN * WSTRIDE];
__device__ float g_areaf[NN];             // exact small-int float sums: order-invariant
__device__ float g_part[NN * NCHUNK];     // per-(mask,chunk) soft sums, single writer
__device__ float g_comp[NN];              // comp_iou (0 at entry)
__device__ int   g_npairs;                // 0 at entry
__device__ unsigned int g_done;           // last-CTA counter (0 at entry)
__device__ unsigned int g_pair_ij[MAXPAIRS];
__device__ float g_pair_d[MAXPAIRS];

// process one quad (index k): ballots + predicated sums + lane-0 STG.128
#define PROC(A, B, K) do {                                               \
    const float s0 = (A).x * (B).x, s1 = (A).y * (B).y;                  \
    const float s2 = (A).z * (B).z, s3 = (A).w * (B).w;                  \
    const bool p0 = s0 > MASK_THR, p1 = s1 > MASK_THR;                   \
    const bool p2 = s2 > MASK_THR, p3 = s3 > MASK_THR;                   \
    const unsigned c0 = __ballot_sync(0xffffffffu, p0);                  \
    const unsigned c1 = __ballot_sync(0xffffffffu, p1);                  \
    const unsigned c2 = __ballot_sync(0xffffffffu, p2);                  \
    const unsigned c3 = __ballot_sync(0xffffffffu, p3);                  \
    if (p0) { ssum += s0; areaf += 1.0f; }                               \
    if (p1) { ssum += s1; areaf += 1.0f; }                               \
    if (p2) { ssum += s2; areaf += 1.0f; }                               \
    if (p3) { ssum += s3; areaf += 1.0f; }                               \
    if (lane == 0) pwB[K] = make_uint4(c0, c1, c2, c3);                  \
} while (0)

// ============================================================
// Kernel 1: decode (exact R14 form — proven LTS-cap floor, 22.0us).
// Warp iteration = 128 consecutive pixels (lane L loads float4 #L),
// 2x unrolled for MLP. Bits packed in ballot order (fixed pixel
// permutation: invariant for AND/popc/area/sums).
// blockIdx.x = mask*12 + chunk.
// ============================================================
__global__ __launch_bounds__(256) void decode_kernel(
    const float* __restrict__ segx,
    const float* __restrict__ segy,
    const int* __restrict__ x_inds,
    const int* __restrict__ y_inds)
{
    const int n    = blockIdx.x / NCHUNK;
    const int c    = blockIdx.x - n * NCHUNK;
    const int tid  = threadIdx.x;
    const int warp = tid >> 5;
    const int lane = tid & 31;

    const int xi = x_inds[n];
    const int yi = y_inds[n];

    const int w0 = c * CHUNKW;
    const int nquads = ((c == NCHUNK - 1) ? (WORDS - w0) : CHUNKW) >> 2;   // 40 or 35

    const float4* __restrict__ bx =
        reinterpret_cast<const float4*>(segx + (size_t)xi * HWPX) + w0 * 8 + lane;
    const float4* __restrict__ by =
        reinterpret_cast<const float4*>(segy + (size_t)yi * HWPX) + w0 * 8 + lane;
    uint4* pwB = reinterpret_cast<uint4*>(g_bits + n * WSTRIDE + w0);

    float ssum  = 0.0f;
    float areaf = 0.0f;

    int k = warp;
    for (; k + 8 < nquads; k += 16) {
        // 4 LDG.128 in flight per thread before first consume
        const float4 a0 = bx[32 * k];
        const float4 b0 = by[32 * k];
        const float4 a1 = bx[32 * (k + 8)];
        const float4 b1 = by[32 * (k + 8)];
        PROC(a0, b0, k);
        PROC(a1, b1, k + 8);
    }
    if (k < nquads) {
        const float4 a0 = bx[32 * k];
        const float4 b0 = by[32 * k];
        PROC(a0, b0, k);
    }

    // last chunk zeroes the pad words [1900,1920)
    if (c == NCHUNK - 1 && tid < WSTRIDE - WORDS)
        g_bits[n * WSTRIDE + WORDS + tid] = 0u;

    // block reduction (8 warps, two floats)
    __shared__ float s_sum[8];
    __shared__ float s_area[8];
#pragma unroll
    for (int off = 16; off > 0; off >>= 1) {
        ssum  += __shfl_down_sync(0xffffffffu, ssum,  off);
        areaf += __shfl_down_sync(0xffffffffu, areaf, off);
    }
    if (lane == 0) { s_sum[warp] = ssum; s_area[warp] = areaf; }
    __syncthreads();
    if (tid == 0) {
        float tsum = 0.0f, tarea = 0.0f;
#pragma unroll
        for (int q = 0; q < 8; q++) { tsum += s_sum[q]; tarea += s_area[q]; }
        g_part[n * NCHUNK + c] = tsum;       // single writer: deterministic
        atomicAdd(&g_areaf[n], tarea);       // exact int-valued float: order-invariant
    }
}

// ============================================================
// Kernel 2: popc (1216-CTA CTA-local pair building, R14 form)
// + last-CTA fused final phase (all reductions order-independent,
// so which CTA runs it is immaterial).
// ============================================================
__global__ __launch_bounds__(256) void popc_kernel(
    const int* __restrict__ labels,
    const float* __restrict__ cate_scores,
    float* __restrict__ out)
{
    __shared__ int s_lab[NN];
    __shared__ unsigned s_pairs[LMAX];
    __shared__ int s_cnt;
    __shared__ unsigned s_last;
    const int tid  = threadIdx.x;
    const int lane = tid & 31;
    const int warp = tid >> 5;

    if (tid == 0) s_cnt = 0;
    for (int q = tid; q < NN; q += 256) s_lab[q] = labels[q];
    __syncthreads();

    const int lo = blockIdx.x * CELLS_PER_CTA;
    const int hi = min(lo + CELLS_PER_CTA, NN * NN);

    // phase 1: thread-granular label gate (<1 iteration)
    for (int p = lo + tid; p < hi; p += 256) {
        const int i = p / NN;
        const int j = p - i * NN;
        if (j > i && s_lab[i] == s_lab[j]) {
            int pos = atomicAdd(&s_cnt, 1);
            s_pairs[pos] = ((unsigned)i << 16) | (unsigned)j;
        }
    }
    __syncthreads();
    const int cnt = s_cnt;

    // phase 2: warp per pair
    for (int q = warp; q < cnt; q += 8) {
        const unsigned ij = s_pairs[q];
        const int i = (int)(ij >> 16);
        const int j = (int)(ij & 0xffffu);

        const uint4* __restrict__ bi = reinterpret_cast<const uint4*>(g_bits + i * WSTRIDE);
        const uint4* __restrict__ bj = reinterpret_cast<const uint4*>(g_bits + j * WSTRIDE);

        int inter = 0;
#pragma unroll 5
        for (int w = lane; w < WSTRIDE / 4; w += 32) {   // 15 iterations
            uint4 a = bi[w];
            uint4 b = bj[w];
            inter += __popc(a.x & b.x) + __popc(a.y & b.y)
                   + __popc(a.z & b.z) + __popc(a.w & b.w);
        }
#pragma unroll
        for (int off = 16; off > 0; off >>= 1)
            inter += __shfl_down_sync(0xffffffffu, inter, off);

        if (lane == 0) {
            float uni = g_areaf[i] + g_areaf[j] - (float)inter;
            float iou = (float)inter / fmaxf(uni, 1e-6f);
            atomicMax(reinterpret_cast<int*>(&g_comp[j]), __float_as_int(iou)); // iou>=0
            int pos = atomicAdd(&g_npairs, 1);
            g_pair_ij[pos] = ij;
            g_pair_d[pos] = iou;
        }
    }

    // ---- last CTA runs the final phase ----
    __threadfence();                                      // release pair data
    if (tid == 0)
        s_last = (atomicAdd(&g_done, 1u) == (unsigned)gridDim.x - 1u);
    __syncthreads();
    if (!s_last) return;
    __threadfence();                                      // acquire side

    __shared__ float s_coef[NN];
    __shared__ float s_score[NN];

    // scores: fixed-order reduce of 12 chunk partials per mask
    for (int n = tid; n < NN; n += 256) {
        float acc = 0.0f;
#pragma unroll
        for (int k = 0; k < NCHUNK; k++) acc += g_part[n * NCHUNK + k];
        s_score[n] = cate_scores[n] * (acc / fmaxf(g_areaf[n], 1.0f));
        s_coef[n] = 1.0f;
    }
    __syncthreads();

    // decay terms -> order-independent min into smem coef
    const int np = g_npairs;
    for (int p = tid; p < np; p += 256) {
        const unsigned ij = g_pair_ij[p];
        const int i = (int)(ij >> 16);
        const int j = (int)(ij & 0xffffu);
        const float d = g_pair_d[p];
        const float cc = g_comp[i];
        const float term = __expf(SIGMA * (cc * cc - d * d));   // > 0
        atomicMin(reinterpret_cast<int*>(&s_coef[j]), __float_as_int(term));
    }
    __syncthreads();

    // output + reset accumulators for next replay
    for (int n = tid; n < NN; n += 256) {
        out[n] = s_score[n] * fminf(s_coef[n], 1.0f);
        g_areaf[n] = 0.0f;
        g_comp[n] = 0.0f;
    }
    if (tid == 0) { g_npairs = 0; g_done = 0u; }
}

extern "C" void kernel_launch(void* const* d_in, const int* in_sizes, int n_in,
                              void* d_out, int out_size)
{
    const float* cate_scores = (const float*)d_in[0];
    const float* segx        = (const float*)d_in[1];
    const float* segy        = (const float*)d_in[2];
    const int*   labels      = (const int*)d_in[3];
    const int*   x_inds      = (const int*)d_in[4];
    const int*   y_inds      = (const int*)d_in[5];
    float* out = (float*)d_out;

    decode_kernel<<<NN * NCHUNK, 256>>>(segx, segy, x_inds, y_inds);
    popc_kernel<<<POPC_BLOCKS, 256>>>(labels, cate_scores, out);
}